// round 17
// baseline (speedup 1.0000x reference)
#include <cuda_runtime.h>
#include <cuda_fp16.h>
#include <cstdint>

#define NW 10
#define DIM 1024
#define HID 64

// W stored as f16 in the HMMA k16 B-fragment layout (geometry validated
// R3-R16), +4096 shorts padding for the depth-1 prefetch overrun.
// WFH = f16(w) ; WFL = f16((w - f16(w)) * 256).
__device__ __align__(16) unsigned short WFH[131072 + 4096];
__device__ __align__(16) unsigned short WFL[131072 + 4096];

// ---------------------------------------------------------------------------
// Circuit kernel (R11 reductions): fused RXRY, CNOT ring as one gather,
// RY1 dropped on qubits 0-2 (summed-out bits; output invariant).
// ---------------------------------------------------------------------------
__device__ __forceinline__ void gate1q(float2* psi, int tid, int bit,
    float g00x, float g00y, float g01x, float g01y,
    float g10x, float g10y, float g11x, float g11y)
{
    const int lowmask = bit - 1;
    const int i0 = ((tid & ~lowmask) << 1) | (tid & lowmask);
    const int i1 = i0 | bit;
    const float2 a = psi[i0], b = psi[i1];
    float2 n0, n1;
    n0.x = g00x*a.x - g00y*a.y + g01x*b.x - g01y*b.y;
    n0.y = g00x*a.y + g00y*a.x + g01x*b.y + g01y*b.x;
    n1.x = g10x*a.x - g10y*a.y + g11x*b.x - g11y*b.y;
    n1.y = g10x*a.y + g10y*a.x + g11x*b.y + g11y*b.x;
    psi[i0] = n0; psi[i1] = n1;
}

__global__ void qsa_circuit(const float* __restrict__ rx0,
                            const float* __restrict__ ry0,
                            const float* __restrict__ ry1)
{
    __shared__ float2 psi[DIM];
    const int tid = threadIdx.x;   // 512
    const int c = blockIdx.x;      // 0..63

    psi[tid]       = make_float2(0.f, 0.f);
    psi[tid + 512] = make_float2(0.f, 0.f);
    __syncthreads();
    if (tid == 0) psi[c] = make_float2(1.f, 0.f);
    __syncthreads();

    for (int j = 0; j < NW; j++) {
        const int bit = 1 << (NW - 1 - j);
        float s1, c1, s2, c2;
        sincosf(0.5f * rx0[j], &s1, &c1);
        sincosf(0.5f * ry0[j], &s2, &c2);
        gate1q(psi, tid, bit,
               c2*c1,  s2*s1,  -s2*c1, -c2*s1,
               s2*c1, -c2*s1,   c2*c1, -s2*s1);
        __syncthreads();
    }
    {   // CNOT ring: one permutation gather
        float2 v[2];
        #pragma unroll
        for (int rep = 0; rep < 2; rep++) {
            int src = tid + rep * 512;
            #pragma unroll
            for (int j = NW - 1; j >= 0; j--) {
                const int cbit = 1 << (NW - 1 - j);
                const int tbit = 1 << (NW - 1 - ((j + 1) % NW));
                if (src & cbit) src ^= tbit;
            }
            v[rep] = psi[src];
        }
        __syncthreads();
        psi[tid]       = v[0];
        psi[tid + 512] = v[1];
        __syncthreads();
    }
    for (int j = 3; j < NW; j++) {
        const int bit = 1 << (NW - 1 - j);
        float s, cc;
        sincosf(0.5f * ry1[j], &s, &cc);
        gate1q(psi, tid, bit, cc, 0.f, -s, 0.f, s, 0.f, cc, 0.f);
        __syncthreads();
    }

    // scatter column c into f16 hi/lo B fragments
    const int chunk = c >> 4;
    const int s16 = (c >> 3) & 1;
    const int lq  = (c & 7) >> 1;
    const int h   = c & 1;
    #pragma unroll
    for (int rep = 0; rep < 2; rep++) {
        const int i = tid + rep * 512;
        const float2 v = psi[i];
        #pragma unroll
        for (int p = 0; p < 2; p++) {
            const float val = p ? v.y : v.x;
            const __half w1 = __float2half(val);
            const __half w2 = __float2half((val - __half2float(w1)) * 256.0f);
            const int n = 2 * i + p;
            const int tile = n >> 3;
            const int idx = ((tile * 64 + (chunk >> 1) * 32 + (n & 7) * 4 + lq) * 4
                             + (chunk & 1) * 2 + s16) * 2 + h;
            WFH[idx] = __half_as_ushort(w1);
            WFL[idx] = __half_as_ushort(w2);
        }
    }
    // zero the padding tiles (256 uint4 per array)
    if (c == 0 && tid < 256) {
        reinterpret_cast<uint4*>(WFH + 131072)[tid] = make_uint4(0,0,0,0);
        reinterpret_cast<uint4*>(WFL + 131072)[tid] = make_uint4(0,0,0,0);
    }
}

// ---------------------------------------------------------------------------
// MMA helpers
// ---------------------------------------------------------------------------
__device__ __forceinline__ void mma_f32acc(float* c,
    const uint32_t* a, uint32_t b0, uint32_t b1)
{
    asm volatile(
        "mma.sync.aligned.m16n8k16.row.col.f32.f16.f16.f32 "
        "{%0,%1,%2,%3}, {%4,%5,%6,%7}, {%8,%9}, {%0,%1,%2,%3};"
        : "+f"(c[0]), "+f"(c[1]), "+f"(c[2]), "+f"(c[3])
        : "r"(a[0]), "r"(a[1]), "r"(a[2]), "r"(a[3]), "r"(b0), "r"(b1));
}

__device__ __forceinline__ void mma_f16acc(uint32_t* c,
    const uint32_t* a, uint32_t b0, uint32_t b1)
{
    asm volatile(
        "mma.sync.aligned.m16n8k16.row.col.f16.f16.f16.f16 "
        "{%0,%1}, {%2,%3,%4,%5}, {%6,%7}, {%0,%1};"
        : "+r"(c[0]), "+r"(c[1])
        : "r"(a[0]), "r"(a[1]), "r"(a[2]), "r"(a[3]), "r"(b0), "r"(b1));
}

// ---------------------------------------------------------------------------
// Main kernel: 32 tokens/CTA (2 groups of 16), 8 warps; warp w owns tiles
// w + 8t (t=0..31) for ALL 32 tokens (B reused 2x -> half L1 traffic/MMA).
// grid = 512, 2 CTAs/SM, depth-1 register prefetch, f16-acc corrections.
// ---------------------------------------------------------------------------
__global__ void __launch_bounds__(256, 2) qsa_main(const float* __restrict__ x,
                                                   float* __restrict__ out)
{
    __shared__ float Y[32][64];
    __shared__ float Q[32][132];
    const int tid  = threadIdx.x;
    const int w    = tid >> 5;
    const int lane = tid & 31;
    const int m0   = blockIdx.x * 32;

    // --- load + L2-normalize 32 tokens ---
    {
        const int tk = tid >> 3;          // token 0..31
        const int pp = tid & 7;           // two float4 each
        const float4* xr = reinterpret_cast<const float4*>(
            x + (size_t)(m0 + tk) * HID) + pp * 2;
        const float4 f0 = xr[0], f1 = xr[1];
        float ssq = f0.x*f0.x + f0.y*f0.y + f0.z*f0.z + f0.w*f0.w
                  + f1.x*f1.x + f1.y*f1.y + f1.z*f1.z + f1.w*f1.w;
        ssq += __shfl_xor_sync(0xffffffffu, ssq, 1);
        ssq += __shfl_xor_sync(0xffffffffu, ssq, 2);
        ssq += __shfl_xor_sync(0xffffffffu, ssq, 4);
        const float rn = rsqrtf(ssq);
        Y[tk][pp*8 + 0] = f0.x * rn;
        Y[tk][pp*8 + 1] = f0.y * rn;
        Y[tk][pp*8 + 2] = f0.z * rn;
        Y[tk][pp*8 + 3] = f0.w * rn;
        Y[tk][pp*8 + 4] = f1.x * rn;
        Y[tk][pp*8 + 5] = f1.y * rn;
        Y[tk][pp*8 + 6] = f1.z * rn;
        Y[tk][pp*8 + 7] = f1.w * rn;
    }
    __syncthreads();

    // --- A fragments: 2 groups x 4 k-chunks x 4 regs, f16 hi (y1) / lo (y2*256) ---
    uint32_t A1[2][4][4], A2[2][4][4];
    {
        const int r0 = lane >> 2;
        const int q2 = (lane & 3) * 2;
        #pragma unroll
        for (int g = 0; g < 2; g++)
            #pragma unroll
            for (int ch = 0; ch < 4; ch++)
                #pragma unroll
                for (int rg = 0; rg < 4; rg++) {
                    const int row = g*16 + r0 + 8*(rg & 1);
                    const int k = ch*16 + q2 + 8*(rg >> 1);
                    const float y0 = Y[row][k], y1 = Y[row][k+1];
                    const __half h0 = __float2half(y0);
                    const __half h1 = __float2half(y1);
                    const __half l0 = __float2half((y0 - __half2float(h0)) * 256.0f);
                    const __half l1 = __float2half((y1 - __half2float(h1)) * 256.0f);
                    A1[g][ch][rg] = ((uint32_t)__half_as_ushort(h1) << 16)
                                  |  __half_as_ushort(h0);
                    A2[g][ch][rg] = ((uint32_t)__half_as_ushort(l1) << 16)
                                  |  __half_as_ushort(l0);
                }
    }

    // --- main loop: 32 tiles, per tile 2 groups x (4 f32acc + 8 f16acc) ---
    float q[2][2][4];
    #pragma unroll
    for (int g = 0; g < 2; g++)
        #pragma unroll
        for (int r = 0; r < 2; r++)
            #pragma unroll
            for (int s = 0; s < 4; s++) q[g][r][s] = 0.f;

    const uint4* pH = reinterpret_cast<const uint4*>(WFH) + w*64 + lane;
    const uint4* pL = reinterpret_cast<const uint4*>(WFL) + w*64 + lane;

    uint4 bh0 = pH[0], bh1 = pH[32];
    uint4 bl0 = pL[0], bl1 = pL[32];

    const float inv256 = 1.0f / 256.0f;

    #pragma unroll 2
    for (int t = 0; t < 32; t++) {
        pH += 512; pL += 512;                       // tile += 8 (padded: safe at t=31)
        const uint4 nh0 = pH[0], nh1 = pH[32];
        const uint4 nl0 = pL[0], nl1 = pL[32];
        const int s = t & 3;

        #pragma unroll
        for (int g = 0; g < 2; g++) {
            float    hh[4] = {0.f,0.f,0.f,0.f};
            uint32_t lh[2] = {0u,0u};
            uint32_t hl[2] = {0u,0u};
            mma_f32acc(hh, A1[g][0], bh0.x, bh0.y);
            mma_f16acc(lh, A2[g][0], bh0.x, bh0.y);
            mma_f16acc(hl, A1[g][0], bl0.x, bl0.y);
            mma_f32acc(hh, A1[g][1], bh0.z, bh0.w);
            mma_f16acc(lh, A2[g][1], bh0.z, bh0.w);
            mma_f16acc(hl, A1[g][1], bl0.z, bl0.w);
            mma_f32acc(hh, A1[g][2], bh1.x, bh1.y);
            mma_f16acc(lh, A2[g][2], bh1.x, bh1.y);
            mma_f16acc(hl, A1[g][2], bl1.x, bl1.y);
            mma_f32acc(hh, A1[g][3], bh1.z, bh1.w);
            mma_f16acc(lh, A2[g][3], bh1.z, bh1.w);
            mma_f16acc(hl, A1[g][3], bl1.z, bl1.w);

            const __half2 s0 = __hadd2(*reinterpret_cast<__half2*>(&lh[0]),
                                       *reinterpret_cast<__half2*>(&hl[0]));
            const __half2 s1 = __hadd2(*reinterpret_cast<__half2*>(&lh[1]),
                                       *reinterpret_cast<__half2*>(&hl[1]));
            const float2 f01 = __half22float2(s0);
            const float2 f23 = __half22float2(s1);
            const float c0 = fmaf(f01.x, inv256, hh[0]);
            const float c1 = fmaf(f01.y, inv256, hh[1]);
            const float c2 = fmaf(f23.x, inv256, hh[2]);
            const float c3 = fmaf(f23.y, inv256, hh[3]);
            q[g][0][s] = fmaf(c0, c0, fmaf(c1, c1, q[g][0][s]));
            q[g][1][s] = fmaf(c2, c2, fmaf(c3, c3, q[g][1][s]));
        }

        bh0 = nh0; bh1 = nh1; bl0 = nl0; bl1 = nl1;
    }

    // --- scatter q into Q[token][j], j = 4w + 32s + (lane&3); disjoint per warp ---
    #pragma unroll
    for (int g = 0; g < 2; g++)
        #pragma unroll
        for (int r = 0; r < 2; r++)
            #pragma unroll
            for (int s = 0; s < 4; s++) {
                const int tok = g*16 + r*8 + (lane >> 2);
                const int j = 4*w + 32*s + (lane & 3);
                Q[tok][j] = q[g][r][s];
            }
    __syncthreads();

    // --- 128-pt WHT per token (warp w: tokens 4w..4w+3), store out[k] = F[k+1] ---
    #pragma unroll
    for (int tt = 0; tt < 4; tt++) {
        const int tok = w*4 + tt;
        float f0 = Q[tok][lane];
        float f1 = Q[tok][lane + 32];
        float f2 = Q[tok][lane + 64];
        float f3 = Q[tok][lane + 96];
        float a0 = f0 + f1, a1 = f0 - f1, a2 = f2 + f3, a3 = f2 - f3;
        f0 = a0 + a2; f2 = a0 - a2; f1 = a1 + a3;
        #pragma unroll
        for (int e = 1; e <= 16; e <<= 1) {
            float p;
            p = __shfl_xor_sync(0xffffffffu, f0, e); f0 = (lane & e) ? (p - f0) : (f0 + p);
            p = __shfl_xor_sync(0xffffffffu, f1, e); f1 = (lane & e) ? (p - f1) : (f1 + p);
            p = __shfl_xor_sync(0xffffffffu, f2, e); f2 = (lane & e) ? (p - f2) : (f2 + p);
        }
        float* orow = out + (size_t)(m0 + tok) * HID;
        if (lane >= 1) orow[lane - 1] = f0;     // F[1..31]  -> k 0..30
        orow[lane + 31] = f1;                   // F[32..63] -> k 31..62
        if (lane == 0) orow[63] = f2;           // F[64]     -> k 63
    }
}

extern "C" void kernel_launch(void* const* d_in, const int* in_sizes, int n_in,
                              void* d_out, int out_size)
{
    const float* x   = (const float*)d_in[0];
    const float* rx0 = (const float*)d_in[1];
    const float* ry0 = (const float*)d_in[2];
    const float* ry1 = (const float*)d_in[3];
    float* out = (float*)d_out;

    const int M = in_sizes[0] / HID;   // 16384 tokens

    qsa_circuit<<<HID, 512>>>(rx0, ry0, ry1);   // W -> f16 hi/lo B fragments
    qsa_main<<<M / 32, 256>>>(x, out);          // 2-group HMMA GEMM + fold + WHT
}